// round 7
// baseline (speedup 1.0000x reference)
#include <cuda_runtime.h>
#include <cuda_fp16.h>
#include <cstdint>
#include <cstddef>

#define N_NODES 8192
#define IN_F    256
#define OUT_F   128
#define ALPHA   0.2f
#define NSPLIT  4
#define JCOLS   (N_NODES / NSPLIT)     // 2048 cols per CTA
#define NC      (JCOLS / 64)           // 32 chunks

// ---------------- device scratch (no allocations allowed) ----------------
__device__ __align__(16) __half  g_WhT[(size_t)OUT_F * N_NODES]; // [n][j] = Wh[j][n]
__device__ float  g_src[N_NODES];
__device__ float  g_dst[N_NODES];
__device__ __align__(16) float4 g_rowpack[N_NODES];  // (-s, exp(s-M), exp(a*s-M), 0)
__device__ __align__(16) float4 g_colpack[N_NODES];  // (d,  exp(d),   exp(a*d),   0)
__device__ __align__(16) float  g_part[(size_t)NSPLIT * N_NODES * OUT_F];
__device__ float  g_rsum[NSPLIT * N_NODES];

__device__ __forceinline__ void cp16(uint32_t dst, const void* src) {
    asm volatile("cp.async.cg.shared.global [%0], [%1], 16;" :: "r"(dst), "l"(src) : "memory");
}
#define CPCOMMIT() asm volatile("cp.async.commit_group;" ::: "memory")
#define CPWAIT1()  asm volatile("cp.async.wait_group 1;" ::: "memory")
#define CPWAIT0()  asm volatile("cp.async.wait_group 0;" ::: "memory")

// ============================================================================
// Kernel 1: Wh = h @ W (fp32 SGEMM, 32-row tiles, 256 CTAs, cp.async double
// buffered), emit WhT fp16 + src/dst via warp shfl reductions.
// ============================================================================
__global__ __launch_bounds__(256) void k1_wh(const float* __restrict__ h,
                                             const float* __restrict__ W,
                                             const float* __restrict__ a_vec) {
    __shared__ float As[2][32][36];   // [buf][row][k] (broadcast reads in compute)
    __shared__ float Bs[2][32][132];  // [buf][k][col]
    __shared__ __half ot[128][40];    // [col][row] staging for transposed write
    __shared__ float srd[64];

    const int tid = threadIdx.x;
    const int tx = tid & 31;          // col group (4 cols)
    const int ty = tid >> 5;          // row group (4 rows)
    const int i0 = blockIdx.x * 32;
    const uint32_t asu = (uint32_t)__cvta_generic_to_shared(&As[0][0][0]);
    const uint32_t bsu = (uint32_t)__cvta_generic_to_shared(&Bs[0][0][0]);

    float acc[4][4];
#pragma unroll
    for (int r = 0; r < 4; ++r)
#pragma unroll
        for (int c = 0; c < 4; ++c) acc[r][c] = 0.f;

    // stage k-block kb into buffer buf
    auto stage = [&](int buf, int kb) {
        int r = tid >> 3, q = tid & 7;
        cp16(asu + (size_t)buf * 4608 + (r * 36 + q * 4) * 4,
             &h[(size_t)(i0 + r) * IN_F + kb + q * 4]);
#pragma unroll
        for (int c = 0; c < 4; ++c) {
            int idx = tid + c * 256;
            int rr = idx >> 5, qq = idx & 31;
            cp16(bsu + (size_t)buf * 16896 + (rr * 132 + qq * 4) * 4,
                 &W[(size_t)(kb + rr) * OUT_F + qq * 4]);
        }
        CPCOMMIT();
    };

    stage(0, 0);
    for (int kb8 = 0; kb8 < 8; ++kb8) {
        const int buf = kb8 & 1;
        if (kb8 < 7) { stage(buf ^ 1, (kb8 + 1) * 32); CPWAIT1(); }
        else CPWAIT0();
        __syncthreads();
#pragma unroll
        for (int kk = 0; kk < 32; ++kk) {
            float4 b = *(float4*)&Bs[buf][kk][tx * 4];
            float ar[4] = {As[buf][ty * 4][kk], As[buf][ty * 4 + 1][kk],
                           As[buf][ty * 4 + 2][kk], As[buf][ty * 4 + 3][kk]};
            float bc[4] = {b.x, b.y, b.z, b.w};
#pragma unroll
            for (int r = 0; r < 4; ++r)
#pragma unroll
                for (int c = 0; c < 4; ++c) acc[r][c] += ar[r] * bc[c];
        }
        __syncthreads();
    }

    // src/dst: each warp owns 4 full rows -> shfl reduce across 32 lanes (cols)
    float a1v[4], a2v[4];
#pragma unroll
    for (int c = 0; c < 4; ++c) {
        a1v[c] = a_vec[tx * 4 + c];
        a2v[c] = a_vec[OUT_F + tx * 4 + c];
    }
#pragma unroll
    for (int r = 0; r < 4; ++r) {
        float s = 0.f, d = 0.f;
#pragma unroll
        for (int c = 0; c < 4; ++c) { s += acc[r][c] * a1v[c]; d += acc[r][c] * a2v[c]; }
#pragma unroll
        for (int off = 16; off > 0; off >>= 1) {
            s += __shfl_xor_sync(0xffffffffu, s, off);
            d += __shfl_xor_sync(0xffffffffu, d, off);
        }
        if (tx == 0) { srd[ty * 4 + r] = s; srd[32 + ty * 4 + r] = d; }
    }

    // fp16 transpose staging
#pragma unroll
    for (int r = 0; r < 4; ++r)
#pragma unroll
        for (int c = 0; c < 4; ++c)
            ot[tx * 4 + c][ty * 4 + r] = __float2half_rn(acc[r][c]);
    __syncthreads();

    // write WhT[n][i0..i0+31]
#pragma unroll
    for (int c = 0; c < 2; ++c) {
        int idx = tid + c * 256;
        int n = idx >> 2, seg = idx & 3;
        *(uint4*)&g_WhT[(size_t)n * N_NODES + i0 + seg * 8] = *(uint4*)&ot[n][seg * 8];
    }
    if (tid < 32) {
        g_src[i0 + tid] = srd[tid];
        g_dst[i0 + tid] = srd[32 + tid];
    }
}

// ============================================================================
// Kernel 2: global max(dst) + per-node exp tables. 1 block x 256 threads.
// ============================================================================
__global__ __launch_bounds__(256) void k2_params() {
    __shared__ float red[256];
    const int tid = threadIdx.x;
    float m = -1e30f;
    for (int i = tid; i < N_NODES; i += 256) m = fmaxf(m, g_dst[i]);
    red[tid] = m;
    __syncthreads();
    for (int s = 128; s > 0; s >>= 1) {
        if (tid < s) red[tid] = fmaxf(red[tid], red[tid + s]);
        __syncthreads();
    }
    const float Dmax = red[0];
    for (int i = tid; i < N_NODES; i += 256) {
        float s = g_src[i], d = g_dst[i];
        float t = s + Dmax;
        float M = (t >= 0.f) ? t : ALPHA * t;     // upper bound of e over the row
        g_rowpack[i] = make_float4(-s, __expf(s - M), __expf(ALPHA * s - M), 0.f);
        g_colpack[i] = make_float4(d, __expf(d), __expf(ALPHA * d), 0.f);
    }
}

// ============================================================================
// Kernel 3: fused masked-softmax weights + fp16-acc HMMA attention GEMM.
// Grid 256 CTAs (64 row-tiles x 4 j-splits) x 512 thr.
// fp16 accumulators drained to fp32 every 2 chunks (K=128 window).
// ============================================================================
#define A_OFF   0                        // w tiles: 2 x 128 x 128B = 32KB
#define B_OFF   32768                    // WhT tiles: 2 x 128 x 128B = 32KB
#define ADJ_OFF 65536                    // adj tiles: 2 x 128 x 256B = 64KB
#define CP_OFF  131072                   // colpack: 2 x 64 x 16B = 2KB
#define RP_OFF  133120                   // rowpack: 128 x 16B = 2KB
#define RSP_OFF 135168                   // row sums: 128 x 4B
#define SMEM3   135680

__device__ __forceinline__ void ldsm4(uint32_t& r0, uint32_t& r1, uint32_t& r2, uint32_t& r3,
                                      uint32_t addr) {
    asm volatile("ldmatrix.sync.aligned.m8n8.x4.shared.b16 {%0,%1,%2,%3}, [%4];"
                 : "=r"(r0), "=r"(r1), "=r"(r2), "=r"(r3) : "r"(addr));
}
__device__ __forceinline__ void mma_f32(float* c, const uint32_t* a, uint32_t b0, uint32_t b1) {
    asm volatile(
        "mma.sync.aligned.m16n8k16.row.col.f32.f16.f16.f32 "
        "{%0,%1,%2,%3}, {%4,%5,%6,%7}, {%8,%9}, {%0,%1,%2,%3};"
        : "+f"(c[0]), "+f"(c[1]), "+f"(c[2]), "+f"(c[3])
        : "r"(a[0]), "r"(a[1]), "r"(a[2]), "r"(a[3]), "r"(b0), "r"(b1));
}
__device__ __forceinline__ void mma_f16(uint32_t* c, const uint32_t* a, uint32_t b0, uint32_t b1) {
    asm volatile(
        "mma.sync.aligned.m16n8k16.row.col.f16.f16.f16.f16 "
        "{%0,%1}, {%2,%3,%4,%5}, {%6,%7}, {%0,%1};"
        : "+r"(c[0]), "+r"(c[1])
        : "r"(a[0]), "r"(a[1]), "r"(a[2]), "r"(a[3]), "r"(b0), "r"(b1));
}

// stage chunk (64 cols) into buffer buf. group1 = colpack+adj, group2 = B.
__device__ __forceinline__ void stage3(uint32_t smu, int tid, int buf,
                                       const int* adj, int i0, size_t j0) {
    if (tid < 64)
        cp16(smu + CP_OFF + buf * 1024 + tid * 16, &g_colpack[j0 + tid]);
#pragma unroll
    for (int c = 0; c < 4; ++c) {
        int idx = tid + c * 512;
        int row = idx >> 4, s = idx & 15;
        cp16(smu + ADJ_OFF + buf * 32768 + row * 256 + s * 16,
             adj + (size_t)(i0 + row) * N_NODES + j0 + s * 4);
    }
    CPCOMMIT();
#pragma unroll
    for (int c = 0; c < 2; ++c) {
        int idx = tid + c * 512;
        int n = idx >> 3, chn = idx & 7;
        cp16(smu + B_OFF + buf * 16384 + n * 128 + ((chn ^ (n & 7)) << 4),
             &g_WhT[(size_t)n * N_NODES + j0 + chn * 8]);
    }
    CPCOMMIT();
}

// weight-gen: thread owns one column (of 64) x 16 rows. conflict-free LDS.
__device__ __forceinline__ void wgen(char* sm, int buf, int rg, int col) {
    const float4 c4 = *(const float4*)(sm + CP_OFF + buf * 1024 + col * 16);
    const char* ab = sm + ADJ_OFF + buf * 32768 + col * 4;
    const float4* rps = (const float4*)(sm + RP_OFF);
    char* aw = sm + A_OFF + buf * 16384 + ((col & 7) * 2);
    const int segc = col >> 3;
    int av[16];
#pragma unroll
    for (int r = 0; r < 16; ++r)
        av[r] = *(const int*)(ab + (rg * 16 + r) * 256);
#pragma unroll
    for (int r = 0; r < 16; ++r) {
        const int row = rg * 16 + r;
        const float4 rp = rps[row];                         // broadcast LDS
        float wv = (c4.x >= rp.x) ? rp.y * c4.y : rp.z * c4.z;
        wv = (av[r] > 0) ? wv : 0.f;
        *(__half*)(aw + row * 128 + ((segc ^ (row & 7)) << 4)) = __float2half_rn(wv);
    }
}

__global__ __launch_bounds__(512, 1) void k3_attn(const int* __restrict__ adj) {
    extern __shared__ char sm[];
    const uint32_t smu = (uint32_t)__cvta_generic_to_shared(sm);
    const int tid = threadIdx.x, lane = tid & 31, warp = tid >> 5;
    const int split = blockIdx.x & 3;
    const int i0 = (blockIdx.x >> 2) * 128;
    const size_t jbase = (size_t)split * JCOLS;

    // wgen identity
    const int rg = warp >> 1;                       // 8 row groups of 16
    const int col = (warp & 1) * 32 + lane;         // column within chunk
    // mma identity: 4(m) x 4(n) warps, each 32x32 out tile
    const int wm = warp & 3, wn = warp >> 2;
    const int g = lane >> 2, t4 = lane & 3;
    // ldmatrix lane addressing
    const int lrA = (lane & 7) + ((lane >> 3) & 1) * 8;   // A: row-in-16
    const int lkA = lane >> 4;                            // A: k-seg select
    const int lrB = (lane & 7) + ((lane >> 4) << 3);      // B: n-row-in-16
    const int lkB = (lane >> 3) & 1;                      // B: k-seg select
    const uint32_t bo = (g == 0) ? 0x3C003C00u : 0u;      // ones B frag (n==0)

    float acc[2][4][4];      // fp32 drain targets
    uint32_t hacc[2][4][2];  // fp16 window accumulators
    float accO[2][4];        // ones-column (row sums), fp32 acc
#pragma unroll
    for (int mt = 0; mt < 2; ++mt) {
#pragma unroll
        for (int nt = 0; nt < 4; ++nt) {
#pragma unroll
            for (int e = 0; e < 4; ++e) acc[mt][nt][e] = 0.f;
            hacc[mt][nt][0] = 0u; hacc[mt][nt][1] = 0u;
        }
#pragma unroll
        for (int e = 0; e < 4; ++e) accO[mt][e] = 0.f;
    }

    // ---- prologue ----
    stage3(smu, tid, 0, adj, i0, jbase);
    if (tid < 128)
        *(float4*)(sm + RP_OFF + tid * 16) = *(const float4*)&g_rowpack[i0 + tid];
    CPWAIT1();
    __syncthreads();
    wgen(sm, 0, rg, col);
    CPWAIT0();
    __syncthreads();

    // ---- main loop ----
    for (int t = 0; t < NC; ++t) {
        const int cur = t & 1, nxt = cur ^ 1;
        const bool more = (t + 1 < NC);
        if (more) stage3(smu, tid, nxt, adj, i0, jbase + (size_t)(t + 1) * 64);

        // MMA on buffer cur (fp16 accumulate)
        {
            const uint32_t aB = smu + A_OFF + cur * 16384;
            const uint32_t bB = smu + B_OFF + cur * 16384;
#pragma unroll
            for (int ks = 0; ks < 4; ++ks) {
                uint32_t a[2][4], b[2][4];
#pragma unroll
                for (int mt = 0; mt < 2; ++mt) {
                    const int row = wm * 32 + mt * 16 + lrA;
                    const int seg = 2 * ks + lkA;
                    ldsm4(a[mt][0], a[mt][1], a[mt][2], a[mt][3],
                          aB + row * 128 + ((seg ^ (row & 7)) << 4));
                }
#pragma unroll
                for (int np = 0; np < 2; ++np) {
                    const int nr = wn * 32 + np * 16 + lrB;
                    const int seg = 2 * ks + lkB;
                    ldsm4(b[np][0], b[np][1], b[np][2], b[np][3],
                          bB + nr * 128 + ((seg ^ (nr & 7)) << 4));
                }
#pragma unroll
                for (int mt = 0; mt < 2; ++mt) {
#pragma unroll
                    for (int np = 0; np < 2; ++np) {
                        mma_f16(hacc[mt][np * 2],     a[mt], b[np][0], b[np][1]);
                        mma_f16(hacc[mt][np * 2 + 1], a[mt], b[np][2], b[np][3]);
                    }
                    if (wn == 0) mma_f32(accO[mt], a[mt], bo, bo);
                }
            }
        }

        // drain fp16 window -> fp32 every 2 chunks (K=128)
        if (t & 1) {
#pragma unroll
            for (int mt = 0; mt < 2; ++mt)
#pragma unroll
                for (int nt = 0; nt < 4; ++nt) {
                    float2 f0 = __half22float2(*(__half2*)&hacc[mt][nt][0]);
                    float2 f1 = __half22float2(*(__half2*)&hacc[mt][nt][1]);
                    acc[mt][nt][0] += f0.x; acc[mt][nt][1] += f0.y;
                    acc[mt][nt][2] += f1.x; acc[mt][nt][3] += f1.y;
                    hacc[mt][nt][0] = 0u;   hacc[mt][nt][1] = 0u;
                }
        }

        if (more) {
            CPWAIT1();             // colpack+adj(t+1) done
            __syncthreads();       // all mma(t) A-tile reads done before wgen writes A[nxt]
            wgen(sm, nxt, rg, col);
            CPWAIT0();             // B(t+1) done
        }
        __syncthreads();
    }

    // ---- epilogue: partial outputs + row sums ----
    {
        float* pp = g_part + (size_t)split * N_NODES * OUT_F;
#pragma unroll
        for (int mt = 0; mt < 2; ++mt) {
            const int row = i0 + wm * 32 + mt * 16 + g;
#pragma unroll
            for (int nt = 0; nt < 4; ++nt) {
                const int cc = wn * 32 + nt * 8 + 2 * t4;
                *(float2*)&pp[(size_t)row * OUT_F + cc] =
                    make_float2(acc[mt][nt][0], acc[mt][nt][1]);
                *(float2*)&pp[(size_t)(row + 8) * OUT_F + cc] =
                    make_float2(acc[mt][nt][2], acc[mt][nt][3]);
            }
        }
    }
    float* rsp = (float*)(sm + RSP_OFF);
    if (wn == 0 && t4 == 0) {
#pragma unroll
        for (int mt = 0; mt < 2; ++mt) {
            rsp[wm * 32 + mt * 16 + g]     = accO[mt][0];
            rsp[wm * 32 + mt * 16 + g + 8] = accO[mt][2];
        }
    }
    __syncthreads();
    if (tid < 128) g_rsum[split * N_NODES + i0 + tid] = rsp[tid];
}

// ============================================================================
// Kernel 4: combine 4 split partials, normalize, ELU, store. 1 float4/thread.
// ============================================================================
__device__ __forceinline__ float elu1(float x) {
    return x > 0.f ? x : (__expf(x) - 1.f);
}

__global__ __launch_bounds__(256) void k4_fin(float* __restrict__ out) {
    int gi = blockIdx.x * 256 + threadIdx.x;      // 262144 threads
    int row = gi >> 5;
    int cof = (gi & 31) * 4;
    const float* pb = g_part + (size_t)row * OUT_F + cof;
    float4 a = *(const float4*)pb;
    float4 b = *(const float4*)(pb + (size_t)N_NODES * OUT_F);
    float4 c = *(const float4*)(pb + 2 * (size_t)N_NODES * OUT_F);
    float4 d = *(const float4*)(pb + 3 * (size_t)N_NODES * OUT_F);
    float s = g_rsum[row] + g_rsum[N_NODES + row]
            + g_rsum[2 * N_NODES + row] + g_rsum[3 * N_NODES + row];
    float rinv = 1.f / s;
    float4 o;
    o.x = elu1((a.x + b.x + c.x + d.x) * rinv);
    o.y = elu1((a.y + b.y + c.y + d.y) * rinv);
    o.z = elu1((a.z + b.z + c.z + d.z) * rinv);
    o.w = elu1((a.w + b.w + c.w + d.w) * rinv);
    *(float4*)(out + (size_t)row * OUT_F + cof) = o;
}

// ============================================================================
extern "C" void kernel_launch(void* const* d_in, const int* in_sizes, int n_in,
                              void* d_out, int out_size) {
    const float* h   = (const float*)d_in[0];
    const int*   adj = (const int*)d_in[1];
    const float* W   = (const float*)d_in[2];
    const float* a   = (const float*)d_in[3];
    float* out = (float*)d_out;
    (void)in_sizes; (void)n_in; (void)out_size;

    cudaFuncSetAttribute(k3_attn, cudaFuncAttributeMaxDynamicSharedMemorySize, SMEM3);

    k1_wh<<<N_NODES / 32, 256>>>(h, W, a);
    k2_params<<<1, 256>>>();
    k3_attn<<<N_NODES / 128 * NSPLIT, 512, SMEM3>>>(adj);
    k4_fin<<<(N_NODES * OUT_F / 4) / 256, 256>>>(out);
}

// round 9
// speedup vs baseline: 1.3645x; 1.3645x over previous
#include <cuda_runtime.h>
#include <cuda_fp16.h>
#include <cstdint>
#include <cstddef>

#define N_NODES 8192
#define IN_F    256
#define OUT_F   128
#define ALPHA   0.2f
#define NSPLIT  4
#define JCOLS   (N_NODES / NSPLIT)     // 2048 cols per CTA
#define NC      (JCOLS / 64)           // 32 chunks

// ---------------- device scratch (no allocations allowed) ----------------
__device__ __align__(16) __half  g_WhT[(size_t)OUT_F * N_NODES]; // [n][j] = Wh[j][n]
__device__ __align__(16) __half  g_WT[(size_t)OUT_F * IN_F];     // [n][k] = W[k][n]
__device__ float  g_src[N_NODES];
__device__ float  g_dst[N_NODES];
__device__ __align__(16) float4 g_rowpack[N_NODES];  // (-s, exp(s-M), exp(a*s-M), 0)
__device__ __align__(16) float4 g_colpack[N_NODES];  // (d,  exp(d),   exp(a*d),   0)
__device__ __align__(16) float  g_part[(size_t)NSPLIT * N_NODES * OUT_F];
__device__ float  g_rsum[NSPLIT * N_NODES];

__device__ __forceinline__ void cp16(uint32_t dst, const void* src) {
    asm volatile("cp.async.cg.shared.global [%0], [%1], 16;" :: "r"(dst), "l"(src) : "memory");
}
#define CPCOMMIT() asm volatile("cp.async.commit_group;" ::: "memory")
#define CPWAIT1()  asm volatile("cp.async.wait_group 1;" ::: "memory")
#define CPWAIT0()  asm volatile("cp.async.wait_group 0;" ::: "memory")

__device__ __forceinline__ void ldsm4(uint32_t& r0, uint32_t& r1, uint32_t& r2, uint32_t& r3,
                                      uint32_t addr) {
    asm volatile("ldmatrix.sync.aligned.m8n8.x4.shared.b16 {%0,%1,%2,%3}, [%4];"
                 : "=r"(r0), "=r"(r1), "=r"(r2), "=r"(r3) : "r"(addr));
}
__device__ __forceinline__ void mma_f32(float* c, const uint32_t* a, uint32_t b0, uint32_t b1) {
    asm volatile(
        "mma.sync.aligned.m16n8k16.row.col.f32.f16.f16.f32 "
        "{%0,%1,%2,%3}, {%4,%5,%6,%7}, {%8,%9}, {%0,%1,%2,%3};"
        : "+f"(c[0]), "+f"(c[1]), "+f"(c[2]), "+f"(c[3])
        : "r"(a[0]), "r"(a[1]), "r"(a[2]), "r"(a[3]), "r"(b0), "r"(b1));
}

// ============================================================================
// Kernel 0: transpose W -> g_WT fp16 [n][k].
// ============================================================================
__global__ __launch_bounds__(256) void k0_wt(const float* __restrict__ W) {
    int idx = blockIdx.x * 256 + threadIdx.x;     // 32768 total
    int k = idx >> 7, n = idx & 127;
    g_WT[(size_t)n * IN_F + k] = __float2half_rn(W[(size_t)k * OUT_F + n]);
}

// ============================================================================
// Kernel 1: Wh = h @ W via HMMA (fp16 in, fp32 acc). 256 CTAs x 32 rows.
// Emits WhT fp16 + src/dst vectors.
// ============================================================================
#define WT_OFF  0                       // 4 panels x 128 n x 128B = 65536
#define AH_OFF  65536                   // 4 panels x 32 rows x 128B = 16384
#define AV_OFF  81920                   // a_vec 256 floats = 1024
#define OT_OFF  82944                   // ot [128][48] halfs = 12288
#define SRD_OFF 95232                   // 64 floats
#define SMEM1   95488

__global__ __launch_bounds__(256, 2) void k1_wh(const float* __restrict__ h,
                                                const float* __restrict__ a_vec) {
    extern __shared__ char sm[];
    const uint32_t smu = (uint32_t)__cvta_generic_to_shared(sm);
    const int tid = threadIdx.x, lane = tid & 31, warp = tid >> 5;
    const int i0 = blockIdx.x * 32;

    // ---- stage WT via cp.async (swizzled panels: [kp][n][128B]) ----
#pragma unroll
    for (int c = 0; c < 16; ++c) {
        int idx = tid + c * 256;                   // 4096 chunks of 16B
        int n = idx >> 5, kc = idx & 31;           // kc: 8-half chunk along k
        int kp = kc >> 3, seg = kc & 7;
        cp16(smu + WT_OFF + kp * 16384 + n * 128 + ((seg ^ (n & 7)) << 4),
             &g_WT[(size_t)n * IN_F + kc * 8]);
    }
    CPCOMMIT();

    // ---- stage h tile (fp32 -> fp16, swizzled panels: [kp][row][128B]) ----
#pragma unroll
    for (int c = 0; c < 8; ++c) {
        int idx = tid + c * 256;                   // 2048 float4s
        int r = idx >> 6, q = idx & 63;            // q: float4 index along k
        float4 v = *(const float4*)&h[(size_t)(i0 + r) * IN_F + q * 4];
        __half2 h01 = __floats2half2_rn(v.x, v.y);
        __half2 h23 = __floats2half2_rn(v.z, v.w);
        uint2 u = make_uint2(*(uint32_t*)&h01, *(uint32_t*)&h23);
        int kp = q >> 4, seg = (q >> 1) & 7, off = (q & 1) * 8;
        *(uint2*)(sm + AH_OFF + kp * 4096 + r * 128 + ((seg ^ (r & 7)) << 4) + off) = u;
    }
    if (tid < 256) *(float*)(sm + AV_OFF + tid * 4) = a_vec[tid];
    if (tid < 64) *(float*)(sm + SRD_OFF + tid * 4) = 0.f;
    CPWAIT0();
    __syncthreads();

    // ---- HMMA: warp grid 2m x 4n, warp tile 16x32, K=256 (16 ks) ----
    const int wm = warp & 1, wn = warp >> 1;
    const int g = lane >> 2, t4 = lane & 3;
    const int lrA = (lane & 7) + ((lane >> 3) & 1) * 8;
    const int lkA = lane >> 4;
    const int lrB = (lane & 7) + ((lane >> 4) << 3);
    const int lkB = (lane >> 3) & 1;

    float acc[4][4];
#pragma unroll
    for (int nt = 0; nt < 4; ++nt)
#pragma unroll
        for (int e = 0; e < 4; ++e) acc[nt][e] = 0.f;

#pragma unroll
    for (int ks = 0; ks < 16; ++ks) {
        const int kp = ks >> 2, ksl = ks & 3;
        uint32_t a[4], b[2][4];
        {
            const int row = wm * 16 + lrA;
            const int seg = ksl * 2 + lkA;
            ldsm4(a[0], a[1], a[2], a[3],
                  smu + AH_OFF + kp * 4096 + row * 128 + ((seg ^ (row & 7)) << 4));
        }
#pragma unroll
        for (int np = 0; np < 2; ++np) {
            const int nr = wn * 32 + np * 16 + lrB;
            const int seg = ksl * 2 + lkB;
            ldsm4(b[np][0], b[np][1], b[np][2], b[np][3],
                  smu + WT_OFF + kp * 16384 + nr * 128 + ((seg ^ (nr & 7)) << 4));
        }
#pragma unroll
        for (int np = 0; np < 2; ++np) {
            mma_f32(acc[np * 2],     a, b[np][0], b[np][1]);
            mma_f32(acc[np * 2 + 1], a, b[np][2], b[np][3]);
        }
    }

    // ---- epilogue: src/dst partials + fp16 transpose staging ----
    const float* av = (const float*)(sm + AV_OFF);
    float* srd = (float*)(sm + SRD_OFF);
    float s0 = 0.f, s1 = 0.f, d0 = 0.f, d1 = 0.f;
#pragma unroll
    for (int nt = 0; nt < 4; ++nt) {
#pragma unroll
        for (int e = 0; e < 2; ++e) {
            const int cc = wn * 32 + nt * 8 + 2 * t4 + e;
            const float a1 = av[cc], a2 = av[128 + cc];
            s0 += acc[nt][e] * a1;     d0 += acc[nt][e] * a2;
            s1 += acc[nt][2 + e] * a1; d1 += acc[nt][2 + e] * a2;
        }
    }
    const int r0 = wm * 16 + g;
    atomicAdd(&srd[r0], s0);      atomicAdd(&srd[r0 + 8], s1);
    atomicAdd(&srd[32 + r0], d0); atomicAdd(&srd[32 + r0 + 8], d1);

    // ot[col][row], row stride 48 halfs (96B)
#pragma unroll
    for (int nt = 0; nt < 4; ++nt)
#pragma unroll
        for (int e = 0; e < 2; ++e) {
            const int cc = wn * 32 + nt * 8 + 2 * t4 + e;
            *(__half*)(sm + OT_OFF + cc * 96 + r0 * 2)       = __float2half_rn(acc[nt][e]);
            *(__half*)(sm + OT_OFF + cc * 96 + (r0 + 8) * 2) = __float2half_rn(acc[nt][2 + e]);
        }
    __syncthreads();

    // coalesced WhT write: 128 n x 4 (8-half segs)
#pragma unroll
    for (int c = 0; c < 2; ++c) {
        int idx = tid + c * 256;
        int n = idx >> 2, seg = idx & 3;
        *(uint4*)&g_WhT[(size_t)n * N_NODES + i0 + seg * 8] =
            *(uint4*)(sm + OT_OFF + n * 96 + seg * 16);
    }
    if (tid < 32) {
        g_src[i0 + tid] = srd[tid];
        g_dst[i0 + tid] = srd[32 + tid];
    }
}

// ============================================================================
// Kernel 2: global max(dst) + per-node exp tables. 1 block x 256 threads.
// ============================================================================
__global__ __launch_bounds__(256) void k2_params() {
    __shared__ float red[256];
    const int tid = threadIdx.x;
    float m = -1e30f;
    for (int i = tid; i < N_NODES; i += 256) m = fmaxf(m, g_dst[i]);
    red[tid] = m;
    __syncthreads();
    for (int s = 128; s > 0; s >>= 1) {
        if (tid < s) red[tid] = fmaxf(red[tid], red[tid + s]);
        __syncthreads();
    }
    const float Dmax = red[0];
    for (int i = tid; i < N_NODES; i += 256) {
        float s = g_src[i], d = g_dst[i];
        float t = s + Dmax;
        float M = (t >= 0.f) ? t : ALPHA * t;     // upper bound of e over the row
        g_rowpack[i] = make_float4(-s, __expf(s - M), __expf(ALPHA * s - M), 0.f);
        g_colpack[i] = make_float4(d, __expf(d), __expf(ALPHA * d), 0.f);
    }
}

// ============================================================================
// Kernel 3: fused masked-softmax weights + HMMA attention GEMM.
// 512 CTAs (128 row-tiles x 4 splits) x 256 thr, 64-row CTA, occupancy 2.
// adj/colpack 3-deep prefetch, A/B double buffered, fp32-acc HMMA.
// ============================================================================
#define A3_OFF   0                       // 2 x 64 x 128B = 16384
#define B3_OFF   16384                   // 2 x 128 x 128B = 32768
#define ADJ3_OFF 49152                   // 3 x 64 x 256B = 49152
#define CP3_OFF  98304                   // 3 x 64 x 16B = 3072
#define RSP3_OFF 101376                  // 64 floats
#define SMEM3    101632

// stage B tile (chunk j0) into buffer bbuf — its own commit group
__device__ __forceinline__ void stage_B(uint32_t smu, int tid, int bbuf, size_t j0) {
#pragma unroll
    for (int c = 0; c < 4; ++c) {
        int idx = tid + c * 256;
        int n = idx >> 3, chn = idx & 7;
        cp16(smu + B3_OFF + bbuf * 16384 + n * 128 + ((chn ^ (n & 7)) << 4),
             &g_WhT[(size_t)n * N_NODES + j0 + chn * 8]);
    }
    CPCOMMIT();
}
// stage adj + colpack (chunk j0) into buffer abuf — its own commit group
__device__ __forceinline__ void stage_ADJ(uint32_t smu, int tid, int abuf,
                                          const int* adj, int i0, size_t j0) {
#pragma unroll
    for (int c = 0; c < 4; ++c) {
        int idx = tid + c * 256;
        int row = idx >> 4, seg = idx & 15;
        cp16(smu + ADJ3_OFF + abuf * 16384 + row * 256 + seg * 16,
             adj + (size_t)(i0 + row) * N_NODES + j0 + seg * 4);
    }
    if (tid < 64)
        cp16(smu + CP3_OFF + abuf * 1024 + tid * 16, &g_colpack[j0 + tid]);
    CPCOMMIT();
}

__global__ __launch_bounds__(256, 2) void k3_attn(const int* __restrict__ adj) {
    extern __shared__ char sm[];
    const uint32_t smu = (uint32_t)__cvta_generic_to_shared(sm);
    const int tid = threadIdx.x, lane = tid & 31, warp = tid >> 5;
    const int split = blockIdx.x & 3;
    const int i0 = (blockIdx.x >> 2) * 64;
    const size_t jbase = (size_t)split * JCOLS;

    // wgen identity: thread owns 2 cols x 8 rows
    const int cp = tid & 31;                  // cols {2cp, 2cp+1}
    const int rg = tid >> 5;                  // rows rg*8 .. +7
    // mma identity: 4m x 2n warps, warp tile 16 rows x 64 cols
    const int wm = warp & 3, wn = warp >> 2;
    const int g = lane >> 2, t4 = lane & 3;
    const int lrA = (lane & 7) + ((lane >> 3) & 1) * 8;
    const int lkA = lane >> 4;
    const int lrB = (lane & 7) + ((lane >> 4) << 3);
    const int lkB = (lane >> 3) & 1;
    const uint32_t bo = (g == 0) ? 0x3C003C00u : 0u;   // ones B frag

    // cache rowpack for owned rows in registers
    float rpx[8], rpy[8], rpz[8];
#pragma unroll
    for (int r = 0; r < 8; ++r) {
        float4 t = g_rowpack[i0 + rg * 8 + r];
        rpx[r] = t.x; rpy[r] = t.y; rpz[r] = t.z;
    }

    float acc[8][4];
    float accO[4];
#pragma unroll
    for (int nt = 0; nt < 8; ++nt)
#pragma unroll
        for (int e = 0; e < 4; ++e) acc[nt][e] = 0.f;
#pragma unroll
    for (int e = 0; e < 4; ++e) accO[e] = 0.f;

    // ---- prologue: adj(0), B(0), adj(1) in flight; drain first two ----
    stage_ADJ(smu, tid, 0, adj, i0, jbase);
    stage_B(smu, tid, 0, jbase);
    stage_ADJ(smu, tid, 1, adj, i0, jbase + 64);
    CPWAIT1();            // adj(0), B(0) done; adj(1) flying
    __syncthreads();

    // ---- main loop ----
    int abuf = 0;         // adj buffer of chunk t (mod 3)
    for (int t = 0; t < NC; ++t) {
        const int cur = t & 1, nxt = cur ^ 1;

        // wgen(t): adj[abuf] + cp[abuf] -> A[cur]
        {
            const float4 c0 = *(const float4*)(sm + CP3_OFF + abuf * 1024 + 2 * cp * 16);
            const float4 c1 = *(const float4*)(sm + CP3_OFF + abuf * 1024 + (2 * cp + 1) * 16);
            const char* ab = sm + ADJ3_OFF + abuf * 16384 + cp * 8;
            char* aw = sm + A3_OFF + cur * 8192;
            const int seg = cp >> 2, off = (cp & 3) * 4;
#pragma unroll
            for (int r = 0; r < 8; ++r) {
                const int row = rg * 8 + r;
                uint2 av = *(const uint2*)(ab + row * 256);
                float w0 = (c0.x >= rpx[r]) ? rpy[r] * c0.y : rpz[r] * c0.z;
                float w1 = (c1.x >= rpx[r]) ? rpy[r] * c1.y : rpz[r] * c1.z;
                if (av.x == 0u) w0 = 0.f;
                if (av.y == 0u) w1 = 0.f;
                __half2 hw = __floats2half2_rn(w0, w1);
                *(uint32_t*)(aw + row * 128 + ((seg ^ (row & 7)) << 4) + off) =
                    *(uint32_t*)&hw;
            }
        }

        if (t + 1 < NC) stage_B(smu, tid, nxt, jbase + (size_t)(t + 1) * 64);
        if (t + 2 < NC) {
            int a2 = abuf + 2; if (a2 >= 3) a2 -= 3;
            stage_ADJ(smu, tid, a2, adj, i0, jbase + (size_t)(t + 2) * 64);
        }
        __syncthreads();   // A[cur] visible for mma

        // mma(t): A[cur] x B[cur]
        {
            const uint32_t aB = smu + A3_OFF + cur * 8192;
            const uint32_t bB = smu + B3_OFF + cur * 16384;
#pragma unroll
            for (int ks = 0; ks < 4; ++ks) {
                uint32_t a[4], b[4][4];
                {
                    const int row = wm * 16 + lrA;
                    const int seg = 2 * ks + lkA;
                    ldsm4(a[0], a[1], a[2], a[3],
                          aB + row * 128 + ((seg ^ (row & 7)) << 4));
                }
#pragma unroll
                for (int np = 0; np < 4; ++np) {
                    const int nr = wn * 64 + np * 16 + lrB;
                    const int seg = 2 * ks + lkB;
                    ldsm4(b[np][0], b[np][1], b[np][2], b[np][3],
                          bB + nr * 128 + ((seg ^ (nr & 7)) << 4));
                }
#pragma unroll
                for (int np = 0; np < 4; ++np) {
                    mma_f32(acc[np * 2],     a, b[np][0], b[np][1]);
                    mma_f32(acc[np * 2 + 1], a, b[np][2], b[np][3]);
                }
                if (wn == 0) mma_f32(accO, a, bo, bo);
            }
        }

        if (t + 2 < NC) CPWAIT1();   // adj(t+1), B(t+1) done; adj(t+2) flying
        else CPWAIT0();
        __syncthreads();

        if (++abuf >= 3) abuf -= 3;
    }

    // ---- epilogue: partial outputs + row sums ----
    {
        float* pp = g_part + (size_t)split * N_NODES * OUT_F;
        const int r0 = i0 + wm * 16 + g;
#pragma unroll
        for (int nt = 0; nt < 8; ++nt) {
            const int cc = wn * 64 + nt * 8 + 2 * t4;
            *(float2*)&pp[(size_t)r0 * OUT_F + cc] =
                make_float2(acc[nt][0], acc[nt][1]);
            *(float2*)&pp[(size_t)(r0 + 8) * OUT_F + cc] =
                make_float2(acc[nt][2], acc[nt][3]);
        }
    }
    float* rsp = (float*)(sm + RSP3_OFF);
    if (wn == 0 && t4 == 0) {
        rsp[wm * 16 + g]     = accO[0];
        rsp[wm * 16 + g + 8] = accO[2];
    }
    __syncthreads();
    if (tid < 64) g_rsum[split * N_NODES + i0 + tid] = rsp[tid];
}

// ============================================================================
// Kernel 4: combine 4 split partials, normalize, ELU, store. 1 float4/thread.
// ============================================================================
__device__ __forceinline__ float elu1(float x) {
    return x > 0.f ? x : (__expf(x) - 1.f);
}

__global__ __launch_bounds__(256) void k4_fin(float* __restrict__ out) {
    int gi = blockIdx.x * 256 + threadIdx.x;      // 262144 threads
    int row = gi >> 5;
    int cof = (gi & 31) * 4;
    const float* pb = g_part + (size_t)row * OUT_F + cof;
    float4 a = *(const float4*)pb;
    float4 b = *(const float4*)(pb + (size_t)N_NODES * OUT_F);
    float4 c = *(const float4*)(pb + 2 * (size_t)N_NODES * OUT_F);
    float4 d = *(const float4*)(pb + 3 * (size_t)N_NODES * OUT_F);
    float s = g_rsum[row] + g_rsum[N_NODES + row]
            + g_rsum[2 * N_NODES + row] + g_rsum[3 * N_NODES + row];
    float rinv = 1.f / s;
    float4 o;
    o.x = elu1((a.x + b.x + c.x + d.x) * rinv);
    o.y = elu1((a.y + b.y + c.y + d.y) * rinv);
    o.z = elu1((a.z + b.z + c.z + d.z) * rinv);
    o.w = elu1((a.w + b.w + c.w + d.w) * rinv);
    *(float4*)(out + (size_t)row * OUT_F + cof) = o;
}

// ============================================================================
extern "C" void kernel_launch(void* const* d_in, const int* in_sizes, int n_in,
                              void* d_out, int out_size) {
    const float* h   = (const float*)d_in[0];
    const int*   adj = (const int*)d_in[1];
    const float* W   = (const float*)d_in[2];
    const float* a   = (const float*)d_in[3];
    float* out = (float*)d_out;
    (void)in_sizes; (void)n_in; (void)out_size;

    cudaFuncSetAttribute(k1_wh, cudaFuncAttributeMaxDynamicSharedMemorySize, SMEM1);
    cudaFuncSetAttribute(k3_attn, cudaFuncAttributeMaxDynamicSharedMemorySize, SMEM3);

    k0_wt<<<(IN_F * OUT_F) / 256, 256>>>(W);
    k1_wh<<<N_NODES / 32, 256, SMEM1>>>(h, a);
    k2_params<<<1, 256>>>();
    k3_attn<<<(N_NODES / 64) * NSPLIT, 256, SMEM3>>>(adj);
    k4_fin<<<(N_NODES * OUT_F / 4) / 256, 256>>>(out);
}